// round 8
// baseline (speedup 1.0000x reference)
#include <cuda_runtime.h>
#include <cuda_bf16.h>
#include <cstdint>

// ---------------------------------------------------------------------------
// GCN 2-layer + FC, aggregation-first + CSR-gather, persistent-megakernel form.
// 3 launches: MEGA1(zero,deg,scan,finalize+pre,fill,gather1) | l1 | MEGA2(gather2,final)
// Grid barriers: generation-counter, all 592 blocks resident (launch_bounds 256,4).
// edge_index is int32.
// ---------------------------------------------------------------------------

#define NMAX 131072
#define EMAX 2097152
#define GRID_B 592          // 148 SMs x 4 blocks; <= residency on 148/152-SM parts
#define TPB 256

__device__ int   g_deg [NMAX];
__device__ int   g_off [NMAX];
__device__ int   g_cur [NMAX];
__device__ int   g_bsum[512];
__device__ int   g_bpre[512];
__device__ int   g_esrc[EMAX];
__device__ float g_dinv[NMAX];
__device__ float g_xs  [NMAX * 16];
__device__ float g_agg1[NMAX * 16];
__device__ float g_hs2 [NMAX * 16];
__device__ float g_agg2[NMAX * 16];

__device__ unsigned g_cnt = 0;
__device__ unsigned g_gen = 0;

// generation-counter grid barrier (all blocks resident; reusable across replays)
__device__ __forceinline__ void gbar() {
    __syncthreads();
    if (threadIdx.x == 0) {
        __threadfence();
        unsigned gen = *((volatile unsigned*)&g_gen);
        if (atomicAdd(&g_cnt, 1u) == gridDim.x - 1u) {
            g_cnt = 0;
            __threadfence();
            atomicAdd(&g_gen, 1u);
        } else {
            while (*((volatile unsigned*)&g_gen) == gen) { }
        }
        __threadfence();
    }
    __syncthreads();
}

// gather: 4 threads/node, thread c owns float4 chunk c, unroll x2 (R5-proven)
__device__ __forceinline__ void gather_loop(const float* __restrict__ msg,
                                            float* __restrict__ agg,
                                            int n, int g0, int gs) {
    const float4* m4 = reinterpret_cast<const float4*>(msg);
    for (int idx = g0; idx < n * 4; idx += gs) {
        int i = idx >> 2, c = idx & 3;
        float4 s = __ldg(m4 + (size_t)i * 4 + c);   // self loop
        int j = g_off[i];
        int end = j + g_deg[i];
        for (; j + 1 < end; j += 2) {
            int r0 = g_esrc[j], r1 = g_esrc[j + 1];
            float4 a = __ldg(m4 + (size_t)r0 * 4 + c);
            float4 b = __ldg(m4 + (size_t)r1 * 4 + c);
            s.x += a.x + b.x; s.y += a.y + b.y; s.z += a.z + b.z; s.w += a.w + b.w;
        }
        if (j < end) {
            int r = g_esrc[j];
            float4 a = __ldg(m4 + (size_t)r * 4 + c);
            s.x += a.x; s.y += a.y; s.z += a.z; s.w += a.w;
        }
        reinterpret_cast<float4*>(agg)[(size_t)i * 4 + c] = s;
    }
}

__global__ void __launch_bounds__(TPB, 4)
k_mega1(const int* __restrict__ src, const int* __restrict__ dst,
        const float* __restrict__ x, int E, int n, int nt) {
    const int gs = gridDim.x * TPB;
    const int g0 = blockIdx.x * TPB + threadIdx.x;

    // S0: zero degrees
    for (int i = g0; i < n; i += gs) g_deg[i] = 0;
    gbar();

    // S1: degree histogram
    for (int e = g0; e < E; e += gs) atomicAdd(&g_deg[dst[e]], 1);
    gbar();

    // S2: per-256-tile exclusive scan (block-local) + tile totals
    {
        __shared__ int wsum[8];
        int lane = threadIdx.x & 31, w = threadIdx.x >> 5;
        for (int tile = blockIdx.x; tile < nt; tile += gridDim.x) {
            int i = tile * 256 + threadIdx.x;
            int v = (i < n) ? g_deg[i] : 0;
            int s = v;
#pragma unroll
            for (int o = 1; o < 32; o <<= 1) {
                int xv = __shfl_up_sync(0xffffffffu, s, o);
                if (lane >= o) s += xv;
            }
            if (lane == 31) wsum[w] = s;
            __syncthreads();
            if (w == 0) {
                int ws = (lane < 8) ? wsum[lane] : 0;
#pragma unroll
                for (int o = 1; o < 8; o <<= 1) {
                    int xv = __shfl_up_sync(0xffffffffu, ws, o);
                    if (lane >= o) ws += xv;
                }
                if (lane < 8) wsum[lane] = ws;
            }
            __syncthreads();
            int base = (w > 0) ? wsum[w - 1] : 0;
            int incl = s + base;
            if (i < n) g_off[i] = incl - v;
            if (threadIdx.x == 255) g_bsum[tile] = incl;
            __syncthreads();                          // wsum reuse next tile
        }
    }
    gbar();

    // S3: scan tile totals (nt <= 512), block 0 only
    if (blockIdx.x == 0) {
        __shared__ int sh[512];
        int t = threadIdx.x;
        int v0 = (t < nt) ? g_bsum[t] : 0;
        int v1 = (t + 256 < nt) ? g_bsum[t + 256] : 0;
        sh[t] = v0; sh[t + 256] = v1;
        __syncthreads();
        for (int o = 1; o < 512; o <<= 1) {
            int a0 = (t >= o) ? sh[t - o] : 0;
            int a1 = (t + 256 >= o) ? sh[t + 256 - o] : 0;
            __syncthreads();
            sh[t] += a0; sh[t + 256] += a1;
            __syncthreads();
        }
        if (t < nt)       g_bpre[t]       = sh[t]       - v0;
        if (t + 256 < nt) g_bpre[t + 256] = sh[t + 256] - v1;
    }
    gbar();

    // S4: finalize offsets/cursors + dinv + xs = x*dinv
    for (int i = g0; i < n; i += gs) {
        int o = g_off[i] + g_bpre[i >> 8];
        g_off[i] = o;
        g_cur[i] = o;
        float dinv = rsqrtf((float)(g_deg[i] + 1));
        g_dinv[i] = dinv;
        const float4* xp = reinterpret_cast<const float4*>(x + (size_t)i * 16);
        float4* xsp = reinterpret_cast<float4*>(g_xs + (size_t)i * 16);
#pragma unroll
        for (int q = 0; q < 4; q++) {
            float4 tv = xp[q];
            tv.x *= dinv; tv.y *= dinv; tv.z *= dinv; tv.w *= dinv;
            xsp[q] = tv;
        }
    }
    gbar();

    // S5: fill CSR adjacency
    for (int e = g0; e < E; e += gs) {
        int t = dst[e];
        int p = atomicAdd(&g_cur[t], 1);
        g_esrc[p] = src[e];
    }
    gbar();

    // S6: gather layer 1
    gather_loop(g_xs, g_agg1, n, g0, gs);
}

// combine layer 1 + both GEMMs + relu (register-heavy: own launch)
__global__ void k_l1(const float* __restrict__ W1, const float* __restrict__ b1,
                     const float* __restrict__ W2, int n) {
    __shared__ float sW1[512];   // [16][32]
    __shared__ float sW2[512];   // [32][16]
    __shared__ float sb1[32];
    for (int i = threadIdx.x; i < 512; i += blockDim.x) { sW1[i] = W1[i]; sW2[i] = W2[i]; }
    if (threadIdx.x < 32) sb1[threadIdx.x] = b1[threadIdx.x];
    __syncthreads();
    int i = blockIdx.x * blockDim.x + threadIdx.x;
    if (i >= n) return;

    float dinv = g_dinv[i];
    float t[16];
    const float4* ap = reinterpret_cast<const float4*>(g_agg1 + (size_t)i * 16);
#pragma unroll
    for (int q = 0; q < 4; q++) {
        float4 a = ap[q];
        t[4*q  ] = a.x * dinv;
        t[4*q+1] = a.y * dinv;
        t[4*q+2] = a.z * dinv;
        t[4*q+3] = a.w * dinv;
    }

    float x2[32];
#pragma unroll
    for (int j = 0; j < 32; j++) {
        float s = sb1[j];
#pragma unroll
        for (int k = 0; k < 16; k++) s = fmaf(t[k], sW1[k*32 + j], s);
        x2[j] = fmaxf(s, 0.f);
    }

    float4* hp = reinterpret_cast<float4*>(g_hs2 + (size_t)i * 16);
#pragma unroll
    for (int q = 0; q < 4; q++) {
        float h[4];
#pragma unroll
        for (int jj = 0; jj < 4; jj++) {
            int j = 4*q + jj;
            float s = 0.f;
#pragma unroll
            for (int k = 0; k < 32; k++) s = fmaf(x2[k], sW2[k*16 + j], s);
            h[jj] = s * dinv;
        }
        hp[q] = make_float4(h[0], h[1], h[2], h[3]);
    }
}

__global__ void __launch_bounds__(TPB, 4)
k_mega2(const float* __restrict__ b2, const float* __restrict__ fcW,
        const float* __restrict__ fcb, float* __restrict__ out, int n) {
    const int gs = gridDim.x * TPB;
    const int g0 = blockIdx.x * TPB + threadIdx.x;

    // S0: gather layer 2
    gather_loop(g_hs2, g_agg2, n, g0, gs);
    gbar();

    // S1: combine layer 2 + relu + FC head (weights via L1-cached broadcast)
    float fb = __ldg(fcb);
    for (int i = g0; i < n; i += gs) {
        float dinv = g_dinv[i];
        float s = fb;
        const float4* ap = reinterpret_cast<const float4*>(g_agg2 + (size_t)i * 16);
#pragma unroll
        for (int q = 0; q < 4; q++) {
            float4 a = ap[q];
            float v0 = fmaxf(fmaf(dinv, a.x, __ldg(b2 + 4*q    )), 0.f);
            float v1 = fmaxf(fmaf(dinv, a.y, __ldg(b2 + 4*q + 1)), 0.f);
            float v2 = fmaxf(fmaf(dinv, a.z, __ldg(b2 + 4*q + 2)), 0.f);
            float v3 = fmaxf(fmaf(dinv, a.w, __ldg(b2 + 4*q + 3)), 0.f);
            s = fmaf(v0, __ldg(fcW + 4*q),
                fmaf(v1, __ldg(fcW + 4*q + 1),
                fmaf(v2, __ldg(fcW + 4*q + 2),
                fmaf(v3, __ldg(fcW + 4*q + 3), s))));
        }
        out[i] = s;
    }
}

extern "C" void kernel_launch(void* const* d_in, const int* in_sizes, int n_in,
                              void* d_out, int out_size) {
    const int*   ei  = (const int*)d_in[0];     // [2, E] int32
    const float* x   = (const float*)d_in[1];   // [N, 16]
    const float* W1  = (const float*)d_in[2];   // [16, 32]
    const float* b1  = (const float*)d_in[3];   // [32]
    const float* W2  = (const float*)d_in[4];   // [32, 16]
    const float* b2  = (const float*)d_in[5];   // [16]
    const float* fcW = (const float*)d_in[6];   // [16, 1]
    const float* fcb = (const float*)d_in[7];   // [1]
    float*       out = (float*)d_out;           // [N, 1]

    const int E = in_sizes[0] / 2;
    const int n = in_sizes[1] / 16;
    const int* src = ei;
    const int* dst = ei + E;
    const int nt = (n + 255) / 256;             // <= 512

    k_mega1<<<GRID_B, TPB>>>(src, dst, x, E, n, nt);
    k_l1   <<<(n + TPB - 1) / TPB, TPB>>>(W1, b1, W2, n);
    k_mega2<<<GRID_B, TPB>>>(b2, fcW, fcb, out, n);
}

// round 9
// speedup vs baseline: 1.1692x; 1.1692x over previous
#include <cuda_runtime.h>
#include <cuda_bf16.h>
#include <cstdint>

// ---------------------------------------------------------------------------
// GCN 2-layer + FC, aggregation-first + CSR-gather (R5 structure, scan-free).
//   CSR segments assigned by warp-aggregated atomicAdd on a global cursor
//   (segment ORDER is irrelevant for gather; only contiguity matters).
//   layer1: agg1[i] = xs[i] + sum_{r in nbr(i)} xs[r],  xs = x*dinv  (16-wide)
//           x2 = relu((dinv*agg1) @ W1 + b1); hs2 = (x2 @ W2)*dinv
//   layer2: agg2[i] = hs2[i] + sum hs2[r]
//           out = relu(dinv*agg2 + b2) @ fcW + fcb
// edge_index is int32.
// ---------------------------------------------------------------------------

#define NMAX 131072
#define EMAX 2097152

__device__ int   g_deg [NMAX];
__device__ int   g_off [NMAX];
__device__ int   g_cur [NMAX];
__device__ int   g_esrc[EMAX];
__device__ int   g_total;
__device__ float g_dinv[NMAX];
__device__ float g_xs  [NMAX * 16];
__device__ float g_agg1[NMAX * 16];
__device__ float g_hs2 [NMAX * 16];
__device__ float g_agg2[NMAX * 16];

__global__ void k_zero(int n) {
    int i = blockIdx.x * blockDim.x + threadIdx.x;
    if (i < n) g_deg[i] = 0;
    if (i == 0) g_total = 0;
}

__global__ void k_deg(const int* __restrict__ dst, int E) {
    int e = blockIdx.x * blockDim.x + threadIdx.x;
    if (e < E) atomicAdd(&g_deg[dst[e]], 1);      // no return -> RED
}

// per node: dinv, xs = x*dinv, and CSR offset via warp-aggregated atomic
__global__ void k_pre(const float* __restrict__ x, int n) {
    int i = blockIdx.x * blockDim.x + threadIdx.x;
    int lane = threadIdx.x & 31;

    int d = (i < n) ? g_deg[i] : 0;
    // inclusive warp scan of d
    int s = d;
#pragma unroll
    for (int o = 1; o < 32; o <<= 1) {
        int v = __shfl_up_sync(0xffffffffu, s, o);
        if (lane >= o) s += v;
    }
    int wtot = __shfl_sync(0xffffffffu, s, 31);
    int base = 0;
    if (lane == 0 && wtot > 0) base = atomicAdd(&g_total, wtot);
    base = __shfl_sync(0xffffffffu, base, 0);
    if (i < n) {
        int o = base + s - d;                     // exclusive prefix
        g_off[i] = o;
        g_cur[i] = o;
        float dinv = rsqrtf((float)(d + 1));
        g_dinv[i] = dinv;
        const float4* xp = reinterpret_cast<const float4*>(x + (size_t)i * 16);
        float4* xsp = reinterpret_cast<float4*>(g_xs + (size_t)i * 16);
#pragma unroll
        for (int q = 0; q < 4; q++) {
            float4 t = xp[q];
            t.x *= dinv; t.y *= dinv; t.z *= dinv; t.w *= dinv;
            xsp[q] = t;
        }
    }
}

// fill CSR adjacency: for each edge, append src to dst's segment
__global__ void k_fill(const int* __restrict__ src, const int* __restrict__ dst, int E) {
    int e = blockIdx.x * blockDim.x + threadIdx.x;
    if (e >= E) return;
    int t = dst[e];
    int p = atomicAdd(&g_cur[t], 1);
    g_esrc[p] = src[e];
}

// gather: 4 threads/node, thread c owns float4 chunk c, unroll x4 (MLP=4)
__device__ __forceinline__ void gather_body(const float* __restrict__ msg,
                                            float* __restrict__ agg, int n) {
    int idx = blockIdx.x * blockDim.x + threadIdx.x;
    int i = idx >> 2, c = idx & 3;
    if (i >= n) return;
    const float4* m4 = reinterpret_cast<const float4*>(msg);
    float4 s = __ldg(m4 + (size_t)i * 4 + c);     // self loop
    int j = g_off[i];
    int end = j + g_deg[i];
    for (; j + 3 < end; j += 4) {
        int r0 = g_esrc[j], r1 = g_esrc[j + 1];
        int r2 = g_esrc[j + 2], r3 = g_esrc[j + 3];
        float4 a = __ldg(m4 + (size_t)r0 * 4 + c);
        float4 b = __ldg(m4 + (size_t)r1 * 4 + c);
        float4 d = __ldg(m4 + (size_t)r2 * 4 + c);
        float4 e = __ldg(m4 + (size_t)r3 * 4 + c);
        s.x += (a.x + b.x) + (d.x + e.x);
        s.y += (a.y + b.y) + (d.y + e.y);
        s.z += (a.z + b.z) + (d.z + e.z);
        s.w += (a.w + b.w) + (d.w + e.w);
    }
    for (; j < end; j++) {
        int r = g_esrc[j];
        float4 a = __ldg(m4 + (size_t)r * 4 + c);
        s.x += a.x; s.y += a.y; s.z += a.z; s.w += a.w;
    }
    reinterpret_cast<float4*>(agg)[(size_t)i * 4 + c] = s;
}

__global__ void k_gather1(int n) { gather_body(g_xs,  g_agg1, n); }
__global__ void k_gather2(int n) { gather_body(g_hs2, g_agg2, n); }

// combine layer 1 + both GEMMs + relu: x2 = relu((dinv*agg1)@W1+b1); hs2 = (x2@W2)*dinv
__global__ void k_l1(const float* __restrict__ W1, const float* __restrict__ b1,
                     const float* __restrict__ W2, int n) {
    __shared__ float sW1[512];   // [16][32]
    __shared__ float sW2[512];   // [32][16]
    __shared__ float sb1[32];
    for (int i = threadIdx.x; i < 512; i += blockDim.x) { sW1[i] = W1[i]; sW2[i] = W2[i]; }
    if (threadIdx.x < 32) sb1[threadIdx.x] = b1[threadIdx.x];
    __syncthreads();
    int i = blockIdx.x * blockDim.x + threadIdx.x;
    if (i >= n) return;

    float dinv = g_dinv[i];
    float t[16];
    const float4* ap = reinterpret_cast<const float4*>(g_agg1 + (size_t)i * 16);
#pragma unroll
    for (int q = 0; q < 4; q++) {
        float4 a = ap[q];
        t[4*q  ] = a.x * dinv;
        t[4*q+1] = a.y * dinv;
        t[4*q+2] = a.z * dinv;
        t[4*q+3] = a.w * dinv;
    }

    float x2[32];
#pragma unroll
    for (int j = 0; j < 32; j++) {
        float s = sb1[j];
#pragma unroll
        for (int k = 0; k < 16; k++) s = fmaf(t[k], sW1[k*32 + j], s);
        x2[j] = fmaxf(s, 0.f);
    }

    float4* hp = reinterpret_cast<float4*>(g_hs2 + (size_t)i * 16);
#pragma unroll
    for (int q = 0; q < 4; q++) {
        float h[4];
#pragma unroll
        for (int jj = 0; jj < 4; jj++) {
            int j = 4*q + jj;
            float s = 0.f;
#pragma unroll
            for (int k = 0; k < 32; k++) s = fmaf(x2[k], sW2[k*16 + j], s);
            h[jj] = s * dinv;
        }
        hp[q] = make_float4(h[0], h[1], h[2], h[3]);
    }
}

// combine layer 2 + relu + FC head
__global__ void k_final(const float* __restrict__ b2, const float* __restrict__ fcW,
                        const float* __restrict__ fcb, float* __restrict__ out, int n) {
    __shared__ float sb[16];
    __shared__ float sw[16];
    if (threadIdx.x < 16) { sb[threadIdx.x] = b2[threadIdx.x]; sw[threadIdx.x] = fcW[threadIdx.x]; }
    __syncthreads();
    int i = blockIdx.x * blockDim.x + threadIdx.x;
    if (i >= n) return;

    float dinv = g_dinv[i];
    float s = fcb[0];
    const float4* ap = reinterpret_cast<const float4*>(g_agg2 + (size_t)i * 16);
#pragma unroll
    for (int q = 0; q < 4; q++) {
        float4 a = ap[q];
        float v0 = fmaxf(fmaf(dinv, a.x, sb[4*q  ]), 0.f);
        float v1 = fmaxf(fmaf(dinv, a.y, sb[4*q+1]), 0.f);
        float v2 = fmaxf(fmaf(dinv, a.z, sb[4*q+2]), 0.f);
        float v3 = fmaxf(fmaf(dinv, a.w, sb[4*q+3]), 0.f);
        s = fmaf(v0, sw[4*q], fmaf(v1, sw[4*q+1], fmaf(v2, sw[4*q+2], fmaf(v3, sw[4*q+3], s))));
    }
    out[i] = s;
}

extern "C" void kernel_launch(void* const* d_in, const int* in_sizes, int n_in,
                              void* d_out, int out_size) {
    const int*   ei  = (const int*)d_in[0];     // [2, E] int32
    const float* x   = (const float*)d_in[1];   // [N, 16]
    const float* W1  = (const float*)d_in[2];   // [16, 32]
    const float* b1  = (const float*)d_in[3];   // [32]
    const float* W2  = (const float*)d_in[4];   // [32, 16]
    const float* b2  = (const float*)d_in[5];   // [16]
    const float* fcW = (const float*)d_in[6];   // [16, 1]
    const float* fcb = (const float*)d_in[7];   // [1]
    float*       out = (float*)d_out;           // [N, 1]

    const int E = in_sizes[0] / 2;
    const int n = in_sizes[1] / 16;
    const int* src = ei;
    const int* dst = ei + E;

    const int T = 256;
    k_zero   <<<(n + T - 1) / T, T>>>(n);
    k_deg    <<<(E + T - 1) / T, T>>>(dst, E);
    k_pre    <<<(n + T - 1) / T, T>>>(x, n);
    k_fill   <<<(E + T - 1) / T, T>>>(src, dst, E);
    k_gather1<<<((long long)n * 4 + T - 1) / T, T>>>(n);
    k_l1     <<<(n + T - 1) / T, T>>>(W1, b1, W2, n);
    k_gather2<<<((long long)n * 4 + T - 1) / T, T>>>(n);
    k_final  <<<(n + T - 1) / T, T>>>(b2, fcW, fcb, out, n);
}